// round 5
// baseline (speedup 1.0000x reference)
#include <cuda_runtime.h>

// Problem constants
#define B_   8
#define C_   512
#define H_   14
#define W_   14
#define P_   196      // H*W positions
#define HS_  1024
#define KC_  144      // 12x12 centers

// Scratch: projections of ALL 196 positions with w1 and w2.
// side_proj[o,b,k,:] == g_q2[b, pos(k)+offset(o), :]  (key restructuring)
__device__ float g_q1[B_ * P_ * HS_];
__device__ float g_q2[B_ * P_ * HS_];

// ---- packed f32x2 helpers (2 FMAs per issue slot on sm_103a) ----
__device__ __forceinline__ unsigned long long pack2(float lo, float hi) {
    unsigned long long r;
    asm("mov.b64 %0, {%1, %2};" : "=l"(r) : "f"(lo), "f"(hi));
    return r;
}
__device__ __forceinline__ void unpack2(unsigned long long v, float& lo, float& hi) {
    asm("mov.b64 {%0, %1}, %2;" : "=f"(lo), "=f"(hi) : "l"(v));
}
__device__ __forceinline__ void fma2(unsigned long long& d, unsigned long long a, unsigned long long b) {
    asm("fma.rn.f32x2 %0, %1, %2, %0;" : "+l"(d) : "l"(a), "l"(b));
}

// =====================================================================
// Phase 1: q[b,p,h] = sum_c x[b,c,p] * w[h,c] + bias[h] for all 196 p.
// Tile: 32 positions x 128 h per CTA, K-chunk 32. 256 threads,
// each thread 2 pos x 8 h (strided j mapping -> conflict-free LDS).
// =====================================================================
__global__ __launch_bounds__(256) void proj_kernel(
    const float* __restrict__ x,
    const float* __restrict__ w1, const float* __restrict__ b1,
    const float* __restrict__ w2, const float* __restrict__ b2)
{
    const int nt  = blockIdx.x;          // 8 h-tiles of 128
    const int mt  = blockIdx.y;          // 7 p-tiles of 32 (224 padded)
    const int b   = blockIdx.z >> 1;
    const int sel = blockIdx.z & 1;
    const float* w    = sel ? w2 : w1;
    const float* bias = sel ? b2 : b1;
    float* q = sel ? g_q2 : g_q1;

    __shared__ float As[32][32];     // [c'][p']
    __shared__ float Ws[32][129];    // [c'][h'] padded (stride 129 -> conflict-free)

    const int tid = threadIdx.x;
    const int tx = tid & 15, ty = tid >> 4;
    const int p0 = mt * 32, h0 = nt * 128;
    const float* xb = x + (size_t)b * C_ * P_;

    unsigned long long acc[2][4];
#pragma unroll
    for (int m = 0; m < 2; m++)
#pragma unroll
        for (int t = 0; t < 4; t++) acc[m][t] = 0ull;

    for (int c0 = 0; c0 < C_; c0 += 32) {
        __syncthreads();
#pragma unroll
        for (int r = 0; r < 4; r++) {            // 32x32 x-tile
            int i  = tid + 256 * r;
            int cc = i >> 5, pp = i & 31;
            int p  = p0 + pp;
            As[cc][pp] = (p < P_) ? xb[(size_t)(c0 + cc) * P_ + p] : 0.f;
        }
#pragma unroll
        for (int r = 0; r < 16; r++) {           // 128h x 32c w-tile (transposed store)
            int i  = tid + 256 * r;
            int cc = i & 31, hh = i >> 5;
            Ws[cc][hh] = w[(size_t)(h0 + hh) * C_ + c0 + cc];
        }
        __syncthreads();
#pragma unroll
        for (int kk = 0; kk < 32; kk++) {
            float a0 = As[kk][ty * 2 + 0], a1 = As[kk][ty * 2 + 1];
            unsigned long long A0 = pack2(a0, a0), A1 = pack2(a1, a1);
#pragma unroll
            for (int tp = 0; tp < 4; tp++) {
                unsigned long long Bp = pack2(Ws[kk][tx + 32 * tp], Ws[kk][tx + 32 * tp + 16]);
                fma2(acc[0][tp], A0, Bp);
                fma2(acc[1][tp], A1, Bp);
            }
        }
    }

#pragma unroll
    for (int m = 0; m < 2; m++) {
        int p = p0 + ty * 2 + m;
        if (p < P_) {
            float* qrow = q + ((size_t)b * P_ + p) * HS_;
#pragma unroll
            for (int tp = 0; tp < 4; tp++) {
                float lo, hi; unpack2(acc[m][tp], lo, hi);
                int hL = h0 + tx + 32 * tp, hH = hL + 16;
                qrow[hL] = lo + bias[hL];
                qrow[hH] = hi + bias[hH];
            }
        }
    }
}

// =====================================================================
// Phase 2: cofe[b,o,i,j] = sum_k q1[b,pc(k),i] * q2[b,ps(k,o),j],
// then row-normalize over j (L2-norm, eps=1e-12).
// CTA = 64 i-rows x full j=1024 (8 chunks of 128). Per-row sumsq kept
// in smem across chunks; raw tile written to gmem (stays L2-hot),
// re-read and scaled in place after the norm is known.
// =====================================================================
__global__ __launch_bounds__(256) void cofe_kernel(float* __restrict__ out)
{
    const int it = blockIdx.x;           // 16 i-tiles of 64
    const int bo = blockIdx.y;           // 72 (b,o) pairs
    const int b  = bo / 9, o = bo % 9;
    const int dy = o / 3 - 1, dx = o % 3 - 1;

    __shared__ float As[16][64];         // q1 tile [k'][i']
    __shared__ float Bs[16][128];        // q2 tile [k'][j']
    __shared__ float ssq[64];

    const int tid = threadIdx.x;
    const int tx = tid & 15, ty = tid >> 4;
    const int i0 = it * 64;
    const float* q1b = g_q1 + (size_t)b * P_ * HS_;
    const float* q2b = g_q2 + (size_t)b * P_ * HS_;
    float* outbo = out + (size_t)bo * HS_ * HS_;

    if (tid < 64) ssq[tid] = 0.f;

    for (int jc = 0; jc < 8; jc++) {
        const int j0 = jc * 128;
        unsigned long long acc[4][4];
#pragma unroll
        for (int m = 0; m < 4; m++)
#pragma unroll
            for (int t = 0; t < 4; t++) acc[m][t] = 0ull;

        for (int k0 = 0; k0 < KC_; k0 += 16) {
            __syncthreads();
#pragma unroll
            for (int r = 0; r < 4; r++) {        // 16k x 64i q1-tile (gather centers)
                int i  = tid + 256 * r;
                int kk = i >> 6, ii = i & 63;
                int k  = k0 + kk;
                int ky = k / 12, kx = k - ky * 12;
                int pos = (ky + 1) * 14 + (kx + 1);
                As[kk][ii] = q1b[(size_t)pos * HS_ + i0 + ii];
            }
#pragma unroll
            for (int r = 0; r < 8; r++) {        // 16k x 128j q2-tile (gather shifted)
                int i  = tid + 256 * r;
                int kk = i >> 7, jj = i & 127;
                int k  = k0 + kk;
                int ky = k / 12, kx = k - ky * 12;
                int pos = (ky + 1 + dy) * 14 + (kx + 1 + dx);
                Bs[kk][jj] = q2b[(size_t)pos * HS_ + j0 + jj];
            }
            __syncthreads();
#pragma unroll
            for (int kk = 0; kk < 16; kk++) {
                unsigned long long A[4], Bp[4];
#pragma unroll
                for (int m = 0; m < 4; m++) {
                    float a = As[kk][ty * 4 + m];
                    A[m] = pack2(a, a);
                }
#pragma unroll
                for (int tp = 0; tp < 4; tp++)
                    Bp[tp] = pack2(Bs[kk][tx + 32 * tp], Bs[kk][tx + 32 * tp + 16]);
#pragma unroll
                for (int m = 0; m < 4; m++)
#pragma unroll
                    for (int tp = 0; tp < 4; tp++)
                        fma2(acc[m][tp], A[m], Bp[tp]);
            }
        }

        // raw write + per-row sum of squares
#pragma unroll
        for (int m = 0; m < 4; m++) {
            float s = 0.f;
            float* orow = outbo + (size_t)(i0 + ty * 4 + m) * HS_ + j0;
#pragma unroll
            for (int tp = 0; tp < 4; tp++) {
                float lo, hi; unpack2(acc[m][tp], lo, hi);
                s += lo * lo + hi * hi;
                orow[tx + 32 * tp]      = lo;
                orow[tx + 32 * tp + 16] = hi;
            }
#pragma unroll
            for (int off = 1; off < 16; off <<= 1)
                s += __shfl_xor_sync(0xffffffffu, s, off, 16);
            if (tx == 0) ssq[ty * 4 + m] += s;   // unique (thread,row) owner -> race-free
        }
    }

    __syncthreads();     // raw writes + ssq visible block-wide
    if (tid < 64) {
        float n = sqrtf(ssq[tid]);
        ssq[tid] = 1.f / fmaxf(n, 1e-12f);
    }
    __syncthreads();

    // scale in place; stripe (256KB) is L2-resident
    float4* g4 = (float4*)(outbo + (size_t)i0 * HS_);
    for (int idx = tid; idx < 64 * HS_ / 4; idx += 256) {
        float4 v = g4[idx];
        float inv = ssq[idx >> 8];               // row = (idx*4)/1024
        v.x *= inv; v.y *= inv; v.z *= inv; v.w *= inv;
        g4[idx] = v;
    }
}

extern "C" void kernel_launch(void* const* d_in, const int* in_sizes, int n_in,
                              void* d_out, int out_size)
{
    const float* x  = (const float*)d_in[0];
    const float* w1 = (const float*)d_in[1];
    const float* b1 = (const float*)d_in[2];
    const float* w2 = (const float*)d_in[3];
    const float* b2 = (const float*)d_in[4];
    float* out = (float*)d_out;

    proj_kernel<<<dim3(8, 7, 16), 256>>>(x, w1, b1, w2, b2);
    cofe_kernel<<<dim3(16, 72), 256>>>(out);
}

// round 10
// speedup vs baseline: 1.4185x; 1.4185x over previous
#include <cuda_runtime.h>
#include <cuda_bf16.h>
#include <cstdint>

#define B_   8
#define C_   512
#define H_   14
#define W_   14
#define P_   196
#define HS_  1024
#define KC_  144
#define KP_  576      // 3 sections of 192 (144 + 48 zero pad)
#define NBO  72

__device__ float g_q1[B_ * P_ * HS_];
__device__ float g_q2[B_ * P_ * HS_];
__device__ __align__(16) __nv_bfloat16 g_Aexp[B_  * HS_ * KP_];
__device__ __align__(16) __nv_bfloat16 g_Bexp[NBO * HS_ * KP_];

// ---- packed f32x2 ----
__device__ __forceinline__ unsigned long long pack2(float lo, float hi) {
    unsigned long long r; asm("mov.b64 %0, {%1, %2};" : "=l"(r) : "f"(lo), "f"(hi)); return r;
}
__device__ __forceinline__ void unpack2(unsigned long long v, float& lo, float& hi) {
    asm("mov.b64 {%0, %1}, %2;" : "=f"(lo), "=f"(hi) : "l"(v));
}
__device__ __forceinline__ void fma2(unsigned long long& d, unsigned long long a, unsigned long long b) {
    asm("fma.rn.f32x2 %0, %1, %2, %0;" : "+l"(d) : "l"(a), "l"(b));
}

// ---- smem / async-copy / mma helpers (all plain sm_80+ features) ----
__device__ __forceinline__ uint32_t smem_u32(const void* p) {
    uint32_t a; asm("{ .reg .u64 t; cvta.to.shared.u64 t, %1; cvt.u32.u64 %0, t; }" : "=r"(a) : "l"(p)); return a;
}
#define CP_ASYNC16(dst, src) \
    asm volatile("cp.async.cg.shared.global [%0], [%1], 16;" :: "r"(dst), "l"(src) : "memory")
#define CP_COMMIT() asm volatile("cp.async.commit_group;" ::: "memory")
#define CP_WAIT1()  asm volatile("cp.async.wait_group 1;" ::: "memory")
#define CP_WAIT0()  asm volatile("cp.async.wait_group 0;" ::: "memory")

__device__ __forceinline__ void ldsm_x4(uint32_t& r0, uint32_t& r1, uint32_t& r2, uint32_t& r3, uint32_t a) {
    asm volatile("ldmatrix.sync.aligned.m8n8.x4.shared.b16 {%0,%1,%2,%3}, [%4];"
                 : "=r"(r0), "=r"(r1), "=r"(r2), "=r"(r3) : "r"(a));
}
__device__ __forceinline__ void mma16816(float* d, const uint32_t* a, uint32_t b0, uint32_t b1) {
    asm volatile("mma.sync.aligned.m16n8k16.row.col.f32.bf16.bf16.f32 "
                 "{%0,%1,%2,%3}, {%4,%5,%6,%7}, {%8,%9}, {%0,%1,%2,%3};"
                 : "+f"(d[0]), "+f"(d[1]), "+f"(d[2]), "+f"(d[3])
                 : "r"(a[0]), "r"(a[1]), "r"(a[2]), "r"(a[3]), "r"(b0), "r"(b1));
}

// ===================== Phase 1: projections (unchanged) =====================
__global__ __launch_bounds__(256) void proj_kernel(
    const float* __restrict__ x,
    const float* __restrict__ w1, const float* __restrict__ b1,
    const float* __restrict__ w2, const float* __restrict__ b2)
{
    const int nt = blockIdx.x, mt = blockIdx.y;
    const int b = blockIdx.z >> 1, sel = blockIdx.z & 1;
    const float* w = sel ? w2 : w1;
    const float* bias = sel ? b2 : b1;
    float* q = sel ? g_q2 : g_q1;

    __shared__ float As[32][32];
    __shared__ float Ws[32][129];
    const int tid = threadIdx.x, tx = tid & 15, ty = tid >> 4;
    const int p0 = mt * 32, h0 = nt * 128;
    const float* xb = x + (size_t)b * C_ * P_;

    unsigned long long acc[2][4];
#pragma unroll
    for (int m = 0; m < 2; m++)
#pragma unroll
        for (int t = 0; t < 4; t++) acc[m][t] = 0ull;

    for (int c0 = 0; c0 < C_; c0 += 32) {
        __syncthreads();
#pragma unroll
        for (int r = 0; r < 4; r++) {
            int i = tid + 256 * r, cc = i >> 5, pp = i & 31, p = p0 + pp;
            As[cc][pp] = (p < P_) ? xb[(size_t)(c0 + cc) * P_ + p] : 0.f;
        }
#pragma unroll
        for (int r = 0; r < 16; r++) {
            int i = tid + 256 * r, cc = i & 31, hh = i >> 5;
            Ws[cc][hh] = w[(size_t)(h0 + hh) * C_ + c0 + cc];
        }
        __syncthreads();
#pragma unroll
        for (int kk = 0; kk < 32; kk++) {
            float a0 = As[kk][ty * 2], a1 = As[kk][ty * 2 + 1];
            unsigned long long A0 = pack2(a0, a0), A1 = pack2(a1, a1);
#pragma unroll
            for (int tp = 0; tp < 4; tp++) {
                unsigned long long Bp = pack2(Ws[kk][tx + 32 * tp], Ws[kk][tx + 32 * tp + 16]);
                fma2(acc[0][tp], A0, Bp);
                fma2(acc[1][tp], A1, Bp);
            }
        }
    }
#pragma unroll
    for (int m = 0; m < 2; m++) {
        int p = p0 + ty * 2 + m;
        if (p < P_) {
            float* qrow = q + ((size_t)b * P_ + p) * HS_;
#pragma unroll
            for (int tp = 0; tp < 4; tp++) {
                float lo, hi; unpack2(acc[m][tp], lo, hi);
                int hL = h0 + tx + 32 * tp, hH = hL + 16;
                qrow[hL] = lo + bias[hL];
                qrow[hH] = hi + bias[hH];
            }
        }
    }
}

// ===================== Phase 1.5: bf16 split + K-major expand =====================
// z < 72: B' rows j for bo=z, sections [Bh|Bl|Bh] (lo at section 1)
// z >= 72: A' rows i for b=z-72, sections [Ah|Ah|Al] (lo at section 2)
__global__ __launch_bounds__(128) void convert_kernel()
{
    __shared__ float tile[KC_][65];
    const int jt = blockIdx.x, z = blockIdx.y, tid = threadIdx.x;
    const float* src; int dy, dx, losec; __nv_bfloat16* dst;
    if (z < NBO) {
        int b = z / 9, o = z % 9;
        dy = o / 3 - 1; dx = o % 3 - 1; losec = 1;
        src = g_q2 + (size_t)b * P_ * HS_;
        dst = g_Bexp + (size_t)z * HS_ * KP_;
    } else {
        int b = z - NBO; dy = 0; dx = 0; losec = 2;
        src = g_q1 + (size_t)b * P_ * HS_;
        dst = g_Aexp + (size_t)b * HS_ * KP_;
    }
    const int j0 = jt * 64;
#pragma unroll
    for (int t = 0; t < 72; t++) {
        int idx = t * 128 + tid, kk = idx >> 6, jj = idx & 63;
        int ky = kk / 12, kx = kk - ky * 12;
        int pos = (ky + 1 + dy) * W_ + (kx + 1 + dx);
        tile[kk][jj] = src[(size_t)pos * HS_ + j0 + jj];
    }
    __syncthreads();
    const int j = tid >> 1, half = tid & 1;
    __nv_bfloat16* drow = dst + (size_t)(j0 + j) * KP_;
#pragma unroll
    for (int u = 0; u < 36; u++) {
        int kp0 = half * 288 + u * 8;
        unsigned short wv[8];
#pragma unroll
        for (int e = 0; e < 8; e++) {
            int kp = kp0 + e, s = kp / 192, kk = kp - s * 192;
            float v = (kk < KC_) ? tile[kk][j] : 0.f;
            __nv_bfloat16 h = __float2bfloat16(v);
            __nv_bfloat16 r = (s == losec) ? __float2bfloat16(v - __bfloat162float(h)) : h;
            wv[e] = *reinterpret_cast<unsigned short*>(&r);
        }
        *(uint4*)(drow + kp0) = *(uint4*)wv;
    }
}

// ===================== Phase 2: mma.sync bf16 GEMM =====================
// CTA 128i x 128j, 8 warps (2x4), warp tile 64x32. K'=576 in 9 chunks
// of 64 (one 128B smem row per matrix row). cp.async double buffer.
// smem: A0[0,16K) A1[16K,32K) B0[32K,48K) B1[48K,64K)
#define GEMM_SMEM 65536

__device__ __forceinline__ void load_chunk(
    const __nv_bfloat16* __restrict__ Ab, const __nv_bfloat16* __restrict__ Bb,
    uint32_t sa, int c, int buf, int tid)
{
    const uint32_t abase = sa + buf * 16384;
    const uint32_t bbase = sa + 32768 + buf * 16384;
#pragma unroll
    for (int r = 0; r < 4; r++) {
        int idx = r * 256 + tid, row = idx >> 3, ch = idx & 7;
        uint32_t dst = abase + row * 128 + (((ch ^ (row & 7)) << 4));
        CP_ASYNC16(dst, (const char*)(Ab + (size_t)row * KP_ + c * 64 + ch * 8));
    }
#pragma unroll
    for (int r = 0; r < 4; r++) {
        int idx = r * 256 + tid, row = idx >> 3, ch = idx & 7;
        uint32_t dst = bbase + row * 128 + (((ch ^ (row & 7)) << 4));
        CP_ASYNC16(dst, (const char*)(Bb + (size_t)row * KP_ + c * 64 + ch * 8));
    }
}

__global__ __launch_bounds__(256, 1) void gemm_kernel(float* __restrict__ out)
{
    extern __shared__ __align__(128) char smem[];
    const uint32_t sa = smem_u32(smem);
    const int tid = threadIdx.x, wid = tid >> 5, lane = tid & 31;
    const int jt = blockIdx.x, it = blockIdx.y, bo = blockIdx.z;
    const int i0 = it * 128, j0 = jt * 128;
    const int wm = wid >> 2, wn = wid & 3;

    const __nv_bfloat16* Ab = g_Aexp + ((size_t)(bo / 9)) * HS_ * KP_ + (size_t)i0 * KP_;
    const __nv_bfloat16* Bb = g_Bexp + (size_t)bo * HS_ * KP_ + (size_t)j0 * KP_;

    load_chunk(Ab, Bb, sa, 0, 0, tid); CP_COMMIT();
    load_chunk(Ab, Bb, sa, 1, 1, tid); CP_COMMIT();

    float d[4][4][4];
#pragma unroll
    for (int mt = 0; mt < 4; mt++)
#pragma unroll
        for (int nt = 0; nt < 4; nt++)
#pragma unroll
            for (int e = 0; e < 4; e++) d[mt][nt][e] = 0.f;

    // ldmatrix per-lane row/chunk components
    const int la_row = (lane & 7) + ((lane >> 3) & 1) * 8;   // A: m-row within 16
    const int la_ch  = lane >> 4;                            // A: k 16B-chunk sel
    const int lb_row = (lane & 7) + (lane >> 4) * 8;         // B: n-row within 16
    const int lb_ch  = (lane >> 3) & 1;                      // B: k 16B-chunk sel

    for (int c = 0; c < 9; c++) {
        const int buf = c & 1;
        if (c == 8) { CP_WAIT0(); } else { CP_WAIT1(); }
        __syncthreads();
        const uint32_t abase = sa + buf * 16384;
        const uint32_t bbase = sa + 32768 + buf * 16384;
#pragma unroll
        for (int ks = 0; ks < 4; ks++) {
            uint32_t a[4][4];
#pragma unroll
            for (int mt = 0; mt < 4; mt++) {
                int row = wm * 64 + mt * 16 + la_row;
                int ch  = ks * 2 + la_ch;
                ldsm_x4(a[mt][0], a[mt][1], a[mt][2], a[mt][3],
                        abase + row * 128 + ((ch ^ (row & 7)) << 4));
            }
            uint32_t bf[2][4];
#pragma unroll
            for (int np = 0; np < 2; np++) {
                int row = wn * 32 + np * 16 + lb_row;
                int ch  = ks * 2 + lb_ch;
                ldsm_x4(bf[np][0], bf[np][1], bf[np][2], bf[np][3],
                        bbase + row * 128 + ((ch ^ (row & 7)) << 4));
            }
#pragma unroll
            for (int mt = 0; mt < 4; mt++)
#pragma unroll
                for (int nt = 0; nt < 4; nt++)
                    mma16816(d[mt][nt], a[mt], bf[nt >> 1][(nt & 1) * 2], bf[nt >> 1][(nt & 1) * 2 + 1]);
        }
        __syncthreads();
        if (c + 2 < 9) { load_chunk(Ab, Bb, sa, c + 2, buf, tid); CP_COMMIT(); }
    }

    // epilogue: raw write. D frag: t holds (row=lane/4, col=(lane&3)*2) and row+8.
    float* obase = out + (size_t)bo * HS_ * HS_;
    const int r0 = i0 + wm * 64 + (lane >> 2);
    const int c0 = j0 + wn * 32 + (lane & 3) * 2;
#pragma unroll
    for (int mt = 0; mt < 4; mt++) {
        int row = r0 + mt * 16;
#pragma unroll
        for (int nt = 0; nt < 4; nt++) {
            int col = c0 + nt * 8;
            *(float2*)(obase + (size_t)row * HS_ + col)       = make_float2(d[mt][nt][0], d[mt][nt][1]);
            *(float2*)(obase + (size_t)(row + 8) * HS_ + col) = make_float2(d[mt][nt][2], d[mt][nt][3]);
        }
    }
}

// ===================== Phase 3: row L2-normalize in place =====================
__global__ __launch_bounds__(256) void normalize_kernel(float* __restrict__ out)
{
    const int it = blockIdx.x, bo = blockIdx.y;
    const int wid = threadIdx.x >> 5, lid = threadIdx.x & 31;
#pragma unroll 1
    for (int pass = 0; pass < 16; pass++) {
        int row = it * 128 + pass * 8 + wid;
        float4* p = (float4*)(out + ((size_t)bo * HS_ + row) * HS_);
        float4 v[8]; float s = 0.f;
#pragma unroll
        for (int f = 0; f < 8; f++) {
            v[f] = p[lid + f * 32];
            s += v[f].x * v[f].x + v[f].y * v[f].y + v[f].z * v[f].z + v[f].w * v[f].w;
        }
#pragma unroll
        for (int off = 16; off > 0; off >>= 1) s += __shfl_xor_sync(0xffffffffu, s, off);
        float inv = 1.f / fmaxf(sqrtf(s), 1e-12f);
#pragma unroll
        for (int f = 0; f < 8; f++) {
            v[f].x *= inv; v[f].y *= inv; v[f].z *= inv; v[f].w *= inv;
            p[lid + f * 32] = v[f];
        }
    }
}

extern "C" void kernel_launch(void* const* d_in, const int* in_sizes, int n_in,
                              void* d_out, int out_size)
{
    const float* x  = (const float*)d_in[0];
    const float* w1 = (const float*)d_in[1];
    const float* b1 = (const float*)d_in[2];
    const float* w2 = (const float*)d_in[3];
    const float* b2 = (const float*)d_in[4];
    float* out = (float*)d_out;

    cudaFuncSetAttribute(gemm_kernel, cudaFuncAttributeMaxDynamicSharedMemorySize, GEMM_SMEM);

    proj_kernel<<<dim3(8, 7, 16), 256>>>(x, w1, b1, w2, b2);
    convert_kernel<<<dim3(16, 80), 128>>>();
    gemm_kernel<<<dim3(8, 8, 72), 256, GEMM_SMEM>>>(out);
    normalize_kernel<<<dim3(8, 72), 256>>>(out);
}